// round 2
// baseline (speedup 1.0000x reference)
#include <cuda_runtime.h>
#include <cuda_bf16.h>
#include <cstdint>
#include <cstddef>

#define T_TOK 8192
#define C_DIM 512
#define H_DIM 128
#define N_REG 128
#define B_MAX 16

// scratch: per-token gate logits, per-(b,region) token bins
__device__ float g_importance[B_MAX * T_TOK];
__device__ int g_cnt[B_MAX * N_REG];
__device__ unsigned short g_bins[(size_t)B_MAX * N_REG * T_TOK];  // 33.5 MB

__device__ __forceinline__ float gelu_exact(float u) {
    // jax.nn.gelu(approximate=False): 0.5*u*(1+erf(u/sqrt(2)))
    return 0.5f * u * (1.0f + erff(u * 0.70710678118654752f));
}

__device__ __forceinline__ uint32_t lds32(const __nv_bfloat16* p) {
    return *reinterpret_cast<const uint32_t*>(p);
}

__device__ __forceinline__ void mma_bf16_16816(float* d, const uint32_t* a, const uint32_t* b) {
    asm volatile(
        "mma.sync.aligned.m16n8k16.row.col.f32.bf16.bf16.f32 "
        "{%0,%1,%2,%3}, {%4,%5,%6,%7}, {%8,%9}, {%0,%1,%2,%3};\n"
        : "+f"(d[0]), "+f"(d[1]), "+f"(d[2]), "+f"(d[3])
        : "r"(a[0]), "r"(a[1]), "r"(a[2]), "r"(a[3]), "r"(b[0]), "r"(b[1]));
}

// ---------------------------------------------------------------------------
// Kernel 1: fused gate. importance[m] = gelu(x[m,:]@W1 + b1)@W2 + b2
// grid = (B*T)/128 blocks, 256 threads (8 warps as 4x2).
// Block tile: 128 tokens x 128 hidden, K=512 in 16 stages of 32.
// ---------------------------------------------------------------------------
__global__ void __launch_bounds__(256)
gate_kernel(const float* __restrict__ x, const float* __restrict__ W1,
            const float* __restrict__ b1, const float* __restrict__ W2,
            const float* __restrict__ b2) {
    __shared__ __align__(16) __nv_bfloat16 As[128][40];   // [token][k] +pad
    __shared__ __align__(16) __nv_bfloat16 Bs[128][40];   // [n][k] (W1^T) +pad
    __shared__ float b1s[128], W2s[128], impS[128];

    const int tid = threadIdx.x;
    const int warp = tid >> 5, lane = tid & 31;
    const int warpM = warp >> 1, warpN = warp & 1;        // warp tile 32r x 64c
    const int g = lane >> 2, tg = lane & 3;
    const int rowBase = blockIdx.x * 128;

    if (tid < 128) { b1s[tid] = b1[tid]; W2s[tid] = W2[tid]; impS[tid] = 0.0f; }

    float acc[2][8][4];
    #pragma unroll
    for (int mt = 0; mt < 2; ++mt)
        #pragma unroll
        for (int nt = 0; nt < 8; ++nt)
            #pragma unroll
            for (int i = 0; i < 4; ++i) acc[mt][nt][i] = 0.0f;

    for (int s = 0; s < 16; ++s) {
        const int k0 = s * 32;
        #pragma unroll
        for (int i = 0; i < 4; ++i) {
            int idx = tid + i * 256;
            int r = idx >> 3, kq = idx & 7;
            float4 v = *reinterpret_cast<const float4*>(
                x + (size_t)(rowBase + r) * C_DIM + k0 + kq * 4);
            *reinterpret_cast<__nv_bfloat162*>(&As[r][kq * 4])     = __floats2bfloat162_rn(v.x, v.y);
            *reinterpret_cast<__nv_bfloat162*>(&As[r][kq * 4 + 2]) = __floats2bfloat162_rn(v.z, v.w);
        }
        #pragma unroll
        for (int i = 0; i < 4; ++i) {
            int idx = tid + i * 256;
            int k = idx >> 5, nq = idx & 31;
            float4 v = *reinterpret_cast<const float4*>(W1 + (size_t)(k0 + k) * H_DIM + nq * 4);
            Bs[nq * 4 + 0][k] = __float2bfloat16(v.x);
            Bs[nq * 4 + 1][k] = __float2bfloat16(v.y);
            Bs[nq * 4 + 2][k] = __float2bfloat16(v.z);
            Bs[nq * 4 + 3][k] = __float2bfloat16(v.w);
        }
        __syncthreads();
        #pragma unroll
        for (int ks = 0; ks < 32; ks += 16) {
            uint32_t a[2][4];
            #pragma unroll
            for (int mt = 0; mt < 2; ++mt) {
                int r0 = warpM * 32 + mt * 16 + g;
                a[mt][0] = lds32(&As[r0][ks + tg * 2]);
                a[mt][1] = lds32(&As[r0 + 8][ks + tg * 2]);
                a[mt][2] = lds32(&As[r0][ks + tg * 2 + 8]);
                a[mt][3] = lds32(&As[r0 + 8][ks + tg * 2 + 8]);
            }
            uint32_t bf[8][2];
            #pragma unroll
            for (int nt = 0; nt < 8; ++nt) {
                int cc = warpN * 64 + nt * 8 + g;
                bf[nt][0] = lds32(&Bs[cc][ks + tg * 2]);
                bf[nt][1] = lds32(&Bs[cc][ks + tg * 2 + 8]);
            }
            #pragma unroll
            for (int mt = 0; mt < 2; ++mt)
                #pragma unroll
                for (int nt = 0; nt < 8; ++nt)
                    mma_bf16_16816(acc[mt][nt], a[mt], bf[nt]);
        }
        __syncthreads();
    }

    // Epilogue: bias + gelu, scale by W2, reduce hidden dim.
    #pragma unroll
    for (int mt = 0; mt < 2; ++mt) {
        float s0 = 0.f, s1 = 0.f;
        #pragma unroll
        for (int nt = 0; nt < 8; ++nt) {
            int c0 = warpN * 64 + nt * 8 + tg * 2;
            s0 += gelu_exact(acc[mt][nt][0] + b1s[c0])     * W2s[c0];
            s0 += gelu_exact(acc[mt][nt][1] + b1s[c0 + 1]) * W2s[c0 + 1];
            s1 += gelu_exact(acc[mt][nt][2] + b1s[c0])     * W2s[c0];
            s1 += gelu_exact(acc[mt][nt][3] + b1s[c0 + 1]) * W2s[c0 + 1];
        }
        s0 += __shfl_xor_sync(0xffffffffu, s0, 1);
        s0 += __shfl_xor_sync(0xffffffffu, s0, 2);
        s1 += __shfl_xor_sync(0xffffffffu, s1, 1);
        s1 += __shfl_xor_sync(0xffffffffu, s1, 2);
        if (tg == 0) {
            int r0 = warpM * 32 + mt * 16 + g;
            atomicAdd(&impS[r0], s0);
            atomicAdd(&impS[r0 + 8], s1);
        }
    }
    __syncthreads();
    if (tid < 128)
        g_importance[rowBase + tid] = impS[tid] + b2[0];   // TEMPERATURE == 1
}

// ---------------------------------------------------------------------------
// Kernel 2a/2b: zero counters, then bin token ids per (batch, region).
// ---------------------------------------------------------------------------
__global__ void zero_kernel() {
    int i = blockIdx.x * blockDim.x + threadIdx.x;
    if (i < B_MAX * N_REG) g_cnt[i] = 0;
}

__global__ void bin_kernel(const int* __restrict__ regions, int BT) {
    int i = blockIdx.x * blockDim.x + threadIdx.x;
    if (i >= BT) return;
    int r = regions[i];
    if (r < 1 || r > N_REG) return;                        // region 0 excluded
    int b = i >> 13;                                       // / T_TOK
    int t = i & (T_TOK - 1);
    int bin = b * N_REG + (r - 1);
    int pos = atomicAdd(&g_cnt[bin], 1);
    g_bins[(size_t)bin * T_TOK + pos] = (unsigned short)t;
}

// ---------------------------------------------------------------------------
// Kernel 3: per-(b,n) softmax over the bin + weighted pooling of x rows.
// grid = (N, B), 256 threads. Typical bin size ~64.
// ---------------------------------------------------------------------------
#define CHUNK 2048

__global__ void __launch_bounds__(256)
pool_kernel(const float* __restrict__ x, float* __restrict__ out) {
    __shared__ float red[256];
    __shared__ unsigned short cidx[CHUNK];
    __shared__ float cw[CHUNK];

    const int tid = threadIdx.x;
    const int n = blockIdx.x, b = blockIdx.y;
    const int bin = b * N_REG + n;
    const int cnt = g_cnt[bin];

    float* op = out + ((size_t)b * N_REG + n) * C_DIM + 2 * tid;
    if (cnt == 0) {
        // reference softmax over all -inf -> NaN
        float qnan = __int_as_float(0x7fc00000);
        op[0] = qnan; op[1] = qnan;
        return;
    }

    const unsigned short* list = g_bins + (size_t)bin * T_TOK;
    const float* imp = g_importance + (size_t)b * T_TOK;

    // Phase A: max logit over the bin
    float lmax = -3.402823466e38f;
    for (int i = tid; i < cnt; i += 256) lmax = fmaxf(lmax, imp[list[i]]);
    red[tid] = lmax;
    __syncthreads();
    #pragma unroll
    for (int s = 128; s > 0; s >>= 1) {
        if (tid < s) red[tid] = fmaxf(red[tid], red[tid + s]);
        __syncthreads();
    }
    const float M = red[0];
    __syncthreads();

    // Phase B: sum of exp
    float lsum = 0.f;
    for (int i = tid; i < cnt; i += 256) lsum += expf(imp[list[i]] - M);
    red[tid] = lsum;
    __syncthreads();
    #pragma unroll
    for (int s = 128; s > 0; s >>= 1) {
        if (tid < s) red[tid] += red[tid + s];
        __syncthreads();
    }
    const float invS = 1.0f / red[0];

    // Phase C: out[b,n,:] = sum_t w_t * x[b,t,:], weights staged in smem.
    const float* xb = x + (size_t)b * T_TOK * C_DIM;
    float ax = 0.f, ay = 0.f;
    for (int base = 0; base < cnt; base += CHUNK) {
        const int m = min(CHUNK, cnt - base);
        __syncthreads();
        for (int i = tid; i < m; i += 256) {
            int t = list[base + i];
            cidx[i] = (unsigned short)t;
            cw[i] = expf(imp[t] - M) * invS;
        }
        __syncthreads();
        #pragma unroll 4
        for (int i = 0; i < m; ++i) {
            float w = cw[i];
            float2 v = *reinterpret_cast<const float2*>(
                xb + (size_t)cidx[i] * C_DIM + 2 * tid);
            ax += w * v.x;
            ay += w * v.y;
        }
    }
    float2 r2; r2.x = ax; r2.y = ay;
    *reinterpret_cast<float2*>(op) = r2;
}

extern "C" void kernel_launch(void* const* d_in, const int* in_sizes, int n_in,
                              void* d_out, int out_size) {
    const float* x       = (const float*)d_in[0];
    const float* W1      = (const float*)d_in[1];
    const float* b1      = (const float*)d_in[2];
    const float* W2      = (const float*)d_in[3];
    const float* b2      = (const float*)d_in[4];
    const int*   regions = (const int*)d_in[5];
    float* out = (float*)d_out;

    const int BT = in_sizes[5];     // B*T
    const int B  = BT / T_TOK;

    gate_kernel<<<BT / 128, 256>>>(x, W1, b1, W2, b2);
    zero_kernel<<<(B_MAX * N_REG + 255) / 256, 256>>>();
    bin_kernel<<<(BT + 255) / 256, 256>>>(regions, BT);
    pool_kernel<<<dim3(N_REG, B), 256>>>(x, out);
}